// round 11
// baseline (speedup 1.0000x reference)
#include <cuda_runtime.h>
#include <cuda_bf16.h>

#define VOCAB   16384
#define WIDTH   256
#define NTOK    8224      // 32 * 257
#define MPAD    8320      // 65 * 128
#define NBATCH  32

#define KTOT    512       // stored per row: [hi(256) | lo(256)]
#define TM      128
#define TN      256
#define BK      64        // bf16 per k-slab => 128B rows
#define NSLAB   12        // 4x hi*hi + 4x hi*lo + 4x lo*hi
#define STAGE   49152     // A 16KB + B 32KB
#define B_OFF   16384
#define DYN_SMEM (2 * STAGE)

// ---------------- scratch (device globals; no runtime alloc) ----------------
__device__ __align__(16) __nv_bfloat16 g_Abf[MPAD * KTOT];    // 8.5 MB
__device__ __align__(16) __nv_bfloat16 g_Bbf[VOCAB * KTOT];   // 16.8 MB
__device__ unsigned long long  g_best[NTOK];
__device__ int                 g_used[VOCAB];
__device__ double              g_loss;

// ---------------- helpers ----------------
__device__ __forceinline__ float block_reduce_sum_256(float v) {
    __shared__ float red[8];
    const int lane = threadIdx.x & 31;
    const int w    = threadIdx.x >> 5;
    #pragma unroll
    for (int o = 16; o > 0; o >>= 1) v += __shfl_xor_sync(0xffffffffu, v, o);
    if (lane == 0) red[w] = v;
    __syncthreads();
    float s = 0.f;
    #pragma unroll
    for (int i = 0; i < 8; i++) s += red[i];
    return s;
}
__device__ __forceinline__ unsigned int f2key(float v) {
    unsigned int u = __float_as_uint(v);
    return (u & 0x80000000u) ? ~u : (u | 0x80000000u);
}
__device__ __forceinline__ unsigned smem_u32(const void* p) {
    unsigned a;
    asm("{ .reg .u64 t; cvta.to.shared.u64 t, %1; cvt.u32.u64 %0, t; }" : "=r"(a) : "l"(p));
    return a;
}
__device__ __forceinline__ void cp16(unsigned dst, const void* src) {
    asm volatile("cp.async.cg.shared.global [%0], [%1], 16;" :: "r"(dst), "l"(src));
}
#define CP_COMMIT() asm volatile("cp.async.commit_group;" ::: "memory")
#define CP_WAIT1()  asm volatile("cp.async.wait_group 1;"  ::: "memory")
#define CP_WAIT0()  asm volatile("cp.async.wait_group 0;"  ::: "memory")

__device__ __forceinline__ void ldsm4(unsigned& r0, unsigned& r1, unsigned& r2, unsigned& r3,
                                      unsigned addr) {
    asm volatile("ldmatrix.sync.aligned.m8n8.x4.shared.b16 {%0,%1,%2,%3}, [%4];"
                 : "=r"(r0), "=r"(r1), "=r"(r2), "=r"(r3) : "r"(addr));
}
__device__ __forceinline__ void mma_bf16(float* d, const unsigned* a, const unsigned* b) {
    asm volatile(
        "mma.sync.aligned.m16n8k16.row.col.f32.bf16.bf16.f32 "
        "{%0,%1,%2,%3}, {%4,%5,%6,%7}, {%8,%9}, {%0,%1,%2,%3};"
        : "+f"(d[0]), "+f"(d[1]), "+f"(d[2]), "+f"(d[3])
        : "r"(a[0]), "r"(a[1]), "r"(a[2]), "r"(a[3]), "r"(b[0]), "r"(b[1]));
}

// slab t -> (A k-offset, B k-offset) in bf16 elements within a row
__device__ __forceinline__ void slab_off(int t, int& kA, int& kB) {
    kA = (t < 8) ? ((t & 3) << 6) : (((t - 8) << 6) + 256);            // hi,hi,lo
    kB = (t < 4) ? (t << 6) : ((t < 8) ? (((t - 4) << 6) + 256)        // hi,lo,hi
                                       : ((t - 8) << 6));
}

// ---------------- K0: reset per-call state ----------------
__global__ void k_init() {
    const int i = blockIdx.x * blockDim.x + threadIdx.x;
    if (i < NTOK)  g_best[i] = 0ull;
    if (i < VOCAB) g_used[i] = 0;
    if (i == 0)    g_loss    = 0.0;
}

// ---------------- K1: gather + normalize + bf16 hi/lo split ----------------
__global__ void k_normalize(const float* __restrict__ cls,
                            const float* __restrict__ patch,
                            const float* __restrict__ W) {
    const int r = blockIdx.x;
    const int c = threadIdx.x;
    float v = 0.f;
    __nv_bfloat16* dst; long long row;
    if (r < MPAD) {
        if (r < NTOK) {
            const int b = r / 257, j = r % 257;
            v = (j == 0) ? cls[b * WIDTH + c]
                         : patch[b * 65536 + c * 256 + (j - 1)];
        }
        dst = g_Abf; row = r;
    } else {
        row = r - MPAD;
        v = W[row * WIDTH + c];
        dst = g_Bbf;
    }
    const float s   = block_reduce_sum_256(v * v);
    const float inv = 1.f / fmaxf(sqrtf(s), 1e-12f);
    const float xn  = v * inv;
    const __nv_bfloat16 hi = __float2bfloat16(xn);
    const float lo = xn - __bfloat162float(hi);
    dst[row * KTOT + c]       = hi;
    dst[row * KTOT + 256 + c] = __float2bfloat16(lo);
}

// ---------------- stage loader: one (A-chunk, B-chunk) slab ----------------
// A tile 128 rows, B tile 256 rows; 128B rows, XOR-16B swizzle
__device__ __forceinline__ void load_slab(unsigned sb, int bm, int bn,
                                          int kA0, int kB0, int tid) {
    const int ck = tid & 7;            // 16B chunk (8 bf16) within 128B row
    const int r0 = tid >> 3;           // 0..31
    const unsigned cswz = (unsigned)(ck << 4);
    #pragma unroll
    for (int i = 0; i < 4; i++) {
        const int lr = r0 + 32 * i;
        const unsigned off = (unsigned)lr * 128u + (cswz ^ (((unsigned)lr & 7u) << 4));
        cp16(sb + off, g_Abf + (long long)(bm + lr) * KTOT + kA0 + ck * 8);
    }
    #pragma unroll
    for (int i = 0; i < 8; i++) {
        const int lr = r0 + 32 * i;
        const unsigned off = (unsigned)lr * 128u + (cswz ^ (((unsigned)lr & 7u) << 4));
        cp16(sb + B_OFF + off, g_Bbf + (long long)(bn + lr) * KTOT + kB0 + ck * 8);
    }
    CP_COMMIT();
}

// ---------------- K2: bf16 mma.sync GEMM (3-term hi/lo split) + argmax ----------------
// CTA 128x256, 8 warps as 2(m) x 4(n), warp tile 64x64
__global__ __launch_bounds__(256, 1)
void k_gemm_mma() {
    extern __shared__ char dsm[];
    __shared__ unsigned long long sbest[TM];

    const unsigned base = smem_u32(dsm);
    const int tid  = threadIdx.x;
    const int lane = tid & 31;
    const int warp = tid >> 5;
    const int wm   = (warp >> 2) * 64;       // warp m-base (2 warps in m)
    const int wn   = (warp & 3) * 64;        // warp n-base (4 warps in n)
    const int bn   = blockIdx.x * TN;
    const int bm   = blockIdx.y * TM;

    float d[4][8][4];
    #pragma unroll
    for (int i = 0; i < 4; i++)
        #pragma unroll
        for (int j = 0; j < 8; j++)
            #pragma unroll
            for (int k = 0; k < 4; k++) d[i][j][k] = 0.f;

    // ldmatrix lane addressing
    const int lsel = lane & 7;
    const int agrp_r = ((lane >> 3) & 1) * 8;   // A: matrices 1,3 -> +8 rows
    const int agrp_k = ((lane >> 4) & 1) * 16;  // A: matrices 2,3 -> +16B k
    const int bgrp_r = ((lane >> 4) & 1) * 8;   // B: matrices 2,3 -> +8 rows
    const int bgrp_k = ((lane >> 3) & 1) * 16;  // B: matrices 1,3 -> +16B k

    // prologue: slabs 0 and 1
    {
        int kA, kB;
        slab_off(0, kA, kB); load_slab(base,         bm, bn, kA, kB, tid);
        slab_off(1, kA, kB); load_slab(base + STAGE, bm, bn, kA, kB, tid);
    }

    #pragma unroll 1
    for (int t = 0; t < NSLAB; t++) {
        const unsigned sA = base + (t & 1) * STAGE;
        const unsigned sB = sA + B_OFF;
        if (t < NSLAB - 1) CP_WAIT1(); else CP_WAIT0();
        __syncthreads();

        #pragma unroll
        for (int g = 0; g < 4; g++) {           // k16 groups within 64-k slab
            const int kb = g * 32;
            unsigned a[4][4], b[8][2];
            #pragma unroll
            for (int mt = 0; mt < 4; mt++) {
                const int row = wm + mt * 16 + lsel + agrp_r;
                const int kk  = kb + agrp_k;
                ldsm4(a[mt][0], a[mt][1], a[mt][2], a[mt][3],
                      sA + (unsigned)row * 128u + ((unsigned)kk ^ (((unsigned)row & 7u) << 4)));
            }
            #pragma unroll
            for (int np = 0; np < 4; np++) {
                const int row = wn + np * 16 + lsel + bgrp_r;
                const int kk  = kb + bgrp_k;
                unsigned r0, r1, r2, r3;
                ldsm4(r0, r1, r2, r3,
                      sB + (unsigned)row * 128u + ((unsigned)kk ^ (((unsigned)row & 7u) << 4)));
                b[np * 2 + 0][0] = r0; b[np * 2 + 0][1] = r1;
                b[np * 2 + 1][0] = r2; b[np * 2 + 1][1] = r3;
            }
            #pragma unroll
            for (int mt = 0; mt < 4; mt++)
                #pragma unroll
                for (int nt = 0; nt < 8; nt++)
                    mma_bf16(d[mt][nt], a[mt], b[nt]);
        }
        __syncthreads();
        if (t + 2 < NSLAB) {
            int kA, kB;
            slab_off(t + 2, kA, kB);
            load_slab(sA, bm, bn, kA, kB, tid);
        }
    }

    // ---- fused argmax epilogue ----
    if (tid < TM) sbest[tid] = 0ull;
    __syncthreads();

    #pragma unroll
    for (int mt = 0; mt < 4; mt++) {
        #pragma unroll
        for (int rh = 0; rh < 2; rh++) {        // d0/d1 = row, d2/d3 = row+8
            const int lrow = wm + mt * 16 + rh * 8 + (lane >> 2);
            float bestv = -2.0f; int bestc = 0;
            #pragma unroll
            for (int nt = 0; nt < 8; nt++) {
                const int c0 = wn + nt * 8 + (lane & 3) * 2;  // ascending col order
                const float v0 = d[mt][nt][rh * 2 + 0];
                const float v1 = d[mt][nt][rh * 2 + 1];
                if (v0 > bestv) { bestv = v0; bestc = c0; }
                if (v1 > bestv) { bestv = v1; bestc = c0 + 1; }
            }
            const unsigned long long pk =
                ((unsigned long long)f2key(bestv) << 32) |
                (unsigned long long)(0xFFFFFFFFu - (unsigned)(bn + bestc));
            atomicMax(&sbest[lrow], pk);
        }
    }
    __syncthreads();

    if (tid < TM) {
        const int grow = bm + tid;
        if (grow < NTOK) atomicMax(&g_best[grow], sbest[tid]);
    }
}

// ---------------- K3: gather W[idx], outputs, loss + usage ----------------
__global__ void k_output(const float* __restrict__ cls,
                         const float* __restrict__ patch,
                         const float* __restrict__ W,
                         float* __restrict__ out) {
    const int t = blockIdx.x;
    const int c = threadIdx.x;
    const int b = t / 257, j = t % 257;

    const int code = (int)(0xFFFFFFFFu - (unsigned int)(g_best[t] & 0xFFFFFFFFull));
    const float w = W[code * WIDTH + c];
    const float x = (j == 0) ? cls[b * WIDTH + c]
                             : patch[b * 65536 + c * 256 + (j - 1)];
    const float dd = w - x;
    const float s = block_reduce_sum_256(dd * dd);
    if (c == 0) {
        atomicAdd(&g_loss, (double)s);
        g_used[code] = 1;
    }
    if (j == 0) out[b * WIDTH + c] = w;                         // fhat_class [B,1,C]
    else        out[8192 + b * 65536 + c * 256 + (j - 1)] = w;  // fhat_patch [B,C,H,W]
}

// ---------------- K4: scalars ----------------
__global__ void k_finalize(float* __restrict__ out) {
    int cnt = 0;
    for (int i = threadIdx.x; i < VOCAB; i += 256) cnt += g_used[i];
    const float s = block_reduce_sum_256((float)cnt);
    if (threadIdx.x == 0) {
        out[2105344] = (float)(1.25 * g_loss / (double)(NTOK * WIDTH));
        out[2105345] = 100.0f * s / (float)VOCAB;
    }
}

// ---------------- launch ----------------
extern "C" void kernel_launch(void* const* d_in, const int* in_sizes, int n_in,
                              void* d_out, int out_size) {
    const float* cls   = nullptr;
    const float* patch = nullptr;
    const float* W     = nullptr;
    for (int i = 0; i < n_in; i++) {
        if      (in_sizes[i] == NBATCH * WIDTH)          cls   = (const float*)d_in[i];
        else if (in_sizes[i] == NBATCH * WIDTH * 256)    patch = (const float*)d_in[i];
        else if (in_sizes[i] == VOCAB * WIDTH)           W     = (const float*)d_in[i];
    }
    float* out = (float*)d_out;

    cudaFuncSetAttribute(k_gemm_mma, cudaFuncAttributeMaxDynamicSharedMemorySize, DYN_SMEM);

    k_init<<<VOCAB / 256, 256>>>();
    k_normalize<<<MPAD + VOCAB, 256>>>(cls, patch, W);
    dim3 grid(VOCAB / TN, MPAD / TM);   // (64, 65)
    k_gemm_mma<<<grid, 256, DYN_SMEM>>>();
    k_output<<<NTOK, 256>>>(cls, patch, W, out);
    k_finalize<<<1, 256>>>(out);
}

// round 12
// speedup vs baseline: 1.1536x; 1.1536x over previous
#include <cuda_runtime.h>
#include <cuda_bf16.h>

#define VOCAB   16384
#define WIDTH   256
#define NTOK    8224      // 32 * 257
#define MPAD    8320      // 65 * 128
#define NBATCH  32

#define KTOT    512       // stored per row: [hi(256) | lo(256)]
#define TM      128
#define TN      128
#define BK      64        // bf16 per k-slab => 128B rows
#define NSLAB   12        // 4x hi*hi + 4x hi*lo + 4x lo*hi
#define STAGE   32768     // A 16KB + B 16KB
#define B_OFF   16384
#define NSTAGE  3
#define DYN_SMEM (NSTAGE * STAGE)   // 96KB -> 2 CTAs/SM

// ---------------- scratch (device globals; no runtime alloc) ----------------
__device__ __align__(16) __nv_bfloat16 g_Abf[MPAD * KTOT];    // 8.5 MB
__device__ __align__(16) __nv_bfloat16 g_Bbf[VOCAB * KTOT];   // 16.8 MB
__device__ unsigned long long  g_best[NTOK];
__device__ int                 g_used[VOCAB];
__device__ double              g_loss;

// ---------------- helpers ----------------
__device__ __forceinline__ float block_reduce_sum_256(float v) {
    __shared__ float red[8];
    const int lane = threadIdx.x & 31;
    const int w    = threadIdx.x >> 5;
    #pragma unroll
    for (int o = 16; o > 0; o >>= 1) v += __shfl_xor_sync(0xffffffffu, v, o);
    if (lane == 0) red[w] = v;
    __syncthreads();
    float s = 0.f;
    #pragma unroll
    for (int i = 0; i < 8; i++) s += red[i];
    return s;
}
__device__ __forceinline__ unsigned int f2key(float v) {
    unsigned int u = __float_as_uint(v);
    return (u & 0x80000000u) ? ~u : (u | 0x80000000u);
}
__device__ __forceinline__ unsigned smem_u32(const void* p) {
    unsigned a;
    asm("{ .reg .u64 t; cvta.to.shared.u64 t, %1; cvt.u32.u64 %0, t; }" : "=r"(a) : "l"(p));
    return a;
}
__device__ __forceinline__ void cp16(unsigned dst, const void* src) {
    asm volatile("cp.async.cg.shared.global [%0], [%1], 16;" :: "r"(dst), "l"(src));
}
#define CP_COMMIT() asm volatile("cp.async.commit_group;" ::: "memory")
#define CP_WAIT1()  asm volatile("cp.async.wait_group 1;"  ::: "memory")
#define CP_WAIT0()  asm volatile("cp.async.wait_group 0;"  ::: "memory")

__device__ __forceinline__ void ldsm4(unsigned& r0, unsigned& r1, unsigned& r2, unsigned& r3,
                                      unsigned addr) {
    asm volatile("ldmatrix.sync.aligned.m8n8.x4.shared.b16 {%0,%1,%2,%3}, [%4];"
                 : "=r"(r0), "=r"(r1), "=r"(r2), "=r"(r3) : "r"(addr));
}
__device__ __forceinline__ void mma_bf16(float* d, const unsigned* a, const unsigned* b) {
    asm volatile(
        "mma.sync.aligned.m16n8k16.row.col.f32.bf16.bf16.f32 "
        "{%0,%1,%2,%3}, {%4,%5,%6,%7}, {%8,%9}, {%0,%1,%2,%3};"
        : "+f"(d[0]), "+f"(d[1]), "+f"(d[2]), "+f"(d[3])
        : "r"(a[0]), "r"(a[1]), "r"(a[2]), "r"(a[3]), "r"(b[0]), "r"(b[1]));
}

// slab t -> (A k-offset, B k-offset) in bf16 elements within a row
__device__ __forceinline__ void slab_off(int t, int& kA, int& kB) {
    kA = (t < 8) ? ((t & 3) << 6) : (((t - 8) << 6) + 256);            // hi,hi,lo
    kB = (t < 4) ? (t << 6) : ((t < 8) ? (((t - 4) << 6) + 256)        // hi,lo,hi
                                       : ((t - 8) << 6));
}

// ---------------- K1: gather + normalize + bf16 hi/lo split (+ state reset) ----------------
__global__ void k_normalize(const float* __restrict__ cls,
                            const float* __restrict__ patch,
                            const float* __restrict__ W) {
    const int r = blockIdx.x;
    const int c = threadIdx.x;
    float v = 0.f;
    __nv_bfloat16* dst; long long row;
    if (r < MPAD) {
        if (r < NTOK) {
            const int b = r / 257, j = r % 257;
            v = (j == 0) ? cls[b * WIDTH + c]
                         : patch[b * 65536 + c * 256 + (j - 1)];
        }
        dst = g_Abf; row = r;
        if (c == 0 && r < NTOK) g_best[r] = 0ull;     // fold k_init here
        if (c == 1 && r == 0)   g_loss   = 0.0;
    } else {
        row = r - MPAD;
        v = W[row * WIDTH + c];
        dst = g_Bbf;
        if (c == 0) g_used[row] = 0;                  // fold k_init here
    }
    const float s   = block_reduce_sum_256(v * v);
    const float inv = 1.f / fmaxf(sqrtf(s), 1e-12f);
    const float xn  = v * inv;
    const __nv_bfloat16 hi = __float2bfloat16(xn);
    const float lo = xn - __bfloat162float(hi);
    dst[row * KTOT + c]       = hi;
    dst[row * KTOT + 256 + c] = __float2bfloat16(lo);
}

// ---------------- stage loader: one (A-chunk, B-chunk) slab ----------------
__device__ __forceinline__ void load_slab(unsigned sb, int bm, int bn,
                                          int kA0, int kB0, int tid) {
    const int ck = tid & 7;            // 16B chunk (8 bf16) within 128B row
    const int r0 = tid >> 3;           // 0..31
    const unsigned cswz = (unsigned)(ck << 4);
    #pragma unroll
    for (int i = 0; i < 4; i++) {
        const int lr = r0 + 32 * i;
        const unsigned off = (unsigned)lr * 128u + (cswz ^ (((unsigned)lr & 7u) << 4));
        cp16(sb + off,         g_Abf + (long long)(bm + lr) * KTOT + kA0 + ck * 8);
        cp16(sb + B_OFF + off, g_Bbf + (long long)(bn + lr) * KTOT + kB0 + ck * 8);
    }
    CP_COMMIT();
}

// ---------------- K2: bf16 mma.sync GEMM (3-term hi/lo split) + argmax ----------------
// CTA 128x128, 8 warps 2(m) x 4(n), warp tile 64x32; 3-stage ring, 1 sync/slab
__global__ __launch_bounds__(256, 2)
void k_gemm_mma() {
    extern __shared__ char dsm[];
    __shared__ unsigned long long sbest[TM];

    const unsigned base = smem_u32(dsm);
    const int tid  = threadIdx.x;
    const int lane = tid & 31;
    const int warp = tid >> 5;
    const int wm   = (warp >> 2) * 64;       // warp m-base (2 warps in m)
    const int wn   = (warp & 3) * 32;        // warp n-base (4 warps in n)
    const int bn   = blockIdx.x * TN;
    const int bm   = blockIdx.y * TM;

    float d[4][4][4];
    #pragma unroll
    for (int i = 0; i < 4; i++)
        #pragma unroll
        for (int j = 0; j < 4; j++)
            #pragma unroll
            for (int k = 0; k < 4; k++) d[i][j][k] = 0.f;

    // ldmatrix lane addressing
    const int lsel = lane & 7;
    const int agrp_r = ((lane >> 3) & 1) * 8;   // A: matrices 1,3 -> +8 rows
    const int agrp_k = ((lane >> 4) & 1) * 16;  // A: matrices 2,3 -> +16B k
    const int bgrp_r = ((lane >> 4) & 1) * 8;   // B: matrices 2,3 -> +8 rows
    const int bgrp_k = ((lane >> 3) & 1) * 16;  // B: matrices 1,3 -> +16B k

    if (tid < TM) sbest[tid] = 0ull;    // epilogue scratch; protected by loop barriers

    // prologue: slabs 0 and 1 into stages 0,1
    {
        int kA, kB;
        slab_off(0, kA, kB); load_slab(base,         bm, bn, kA, kB, tid);
        slab_off(1, kA, kB); load_slab(base + STAGE, bm, bn, kA, kB, tid);
    }

    int s_cur = 0, s_nxt = 2;           // stage of slab t, stage for slab t+2
    #pragma unroll 1
    for (int t = 0; t < NSLAB; t++) {
        const unsigned sA = base + s_cur * STAGE;
        const unsigned sB = sA + B_OFF;
        if (t < NSLAB - 1) CP_WAIT1(); else CP_WAIT0();   // slab t resident
        __syncthreads();   // also: everyone done reading the stage we refill below

        if (t + 2 < NSLAB) {            // refill stage s_nxt (= stage of slab t-1)
            int kA, kB;
            slab_off(t + 2, kA, kB);
            load_slab(base + s_nxt * STAGE, bm, bn, kA, kB, tid);
        }
        if (++s_cur == NSTAGE) s_cur = 0;
        if (++s_nxt == NSTAGE) s_nxt = 0;

        #pragma unroll
        for (int g = 0; g < 4; g++) {           // k16 groups within 64-k slab
            const int kb = g * 32;
            unsigned a[4][4], b[4][2];
            #pragma unroll
            for (int mt = 0; mt < 4; mt++) {
                const int row = wm + mt * 16 + lsel + agrp_r;
                const int kk  = kb + agrp_k;
                ldsm4(a[mt][0], a[mt][1], a[mt][2], a[mt][3],
                      sA + (unsigned)row * 128u + ((unsigned)kk ^ (((unsigned)row & 7u) << 4)));
            }
            #pragma unroll
            for (int np = 0; np < 2; np++) {
                const int row = wn + np * 16 + lsel + bgrp_r;
                const int kk  = kb + bgrp_k;
                unsigned r0, r1, r2, r3;
                ldsm4(r0, r1, r2, r3,
                      sB + (unsigned)row * 128u + ((unsigned)kk ^ (((unsigned)row & 7u) << 4)));
                b[np * 2 + 0][0] = r0; b[np * 2 + 0][1] = r1;
                b[np * 2 + 1][0] = r2; b[np * 2 + 1][1] = r3;
            }
            #pragma unroll
            for (int mt = 0; mt < 4; mt++)
                #pragma unroll
                for (int nt = 0; nt < 4; nt++)
                    mma_bf16(d[mt][nt], a[mt], b[nt]);
        }
    }

    // ---- fused argmax epilogue (sbest pre-zeroed; all writes precede barriers above) ----
    #pragma unroll
    for (int mt = 0; mt < 4; mt++) {
        #pragma unroll
        for (int rh = 0; rh < 2; rh++) {        // d0/d1 = row, d2/d3 = row+8
            const int lrow = wm + mt * 16 + rh * 8 + (lane >> 2);
            float bestv = -2.0f; int bestc = 0;
            #pragma unroll
            for (int nt = 0; nt < 4; nt++) {
                const int c0 = wn + nt * 8 + (lane & 3) * 2;  // ascending col order
                const float v0 = d[mt][nt][rh * 2 + 0];
                const float v1 = d[mt][nt][rh * 2 + 1];
                if (v0 > bestv) { bestv = v0; bestc = c0; }
                if (v1 > bestv) { bestv = v1; bestc = c0 + 1; }
            }
            const unsigned long long pk =
                ((unsigned long long)f2key(bestv) << 32) |
                (unsigned long long)(0xFFFFFFFFu - (unsigned)(bn + bestc));
            atomicMax(&sbest[lrow], pk);
        }
    }
    __syncthreads();

    if (tid < TM) {
        const int grow = bm + tid;
        if (grow < NTOK) atomicMax(&g_best[grow], sbest[tid]);
    }
}

// ---------------- K3: gather W[idx], outputs, loss + usage ----------------
__global__ void k_output(const float* __restrict__ cls,
                         const float* __restrict__ patch,
                         const float* __restrict__ W,
                         float* __restrict__ out) {
    const int t = blockIdx.x;
    const int c = threadIdx.x;
    const int b = t / 257, j = t % 257;

    const int code = (int)(0xFFFFFFFFu - (unsigned int)(g_best[t] & 0xFFFFFFFFull));
    const float w = W[code * WIDTH + c];
    const float x = (j == 0) ? cls[b * WIDTH + c]
                             : patch[b * 65536 + c * 256 + (j - 1)];
    const float dd = w - x;
    const float s = block_reduce_sum_256(dd * dd);
    if (c == 0) {
        atomicAdd(&g_loss, (double)s);
        g_used[code] = 1;
    }
    if (j == 0) out[b * WIDTH + c] = w;                         // fhat_class [B,1,C]
    else        out[8192 + b * 65536 + c * 256 + (j - 1)] = w;  // fhat_patch [B,C,H,W]
}

// ---------------- K4: scalars ----------------
__global__ void k_finalize(float* __restrict__ out) {
    int cnt = 0;
    for (int i = threadIdx.x; i < VOCAB; i += 256) cnt += g_used[i];
    const float s = block_reduce_sum_256((float)cnt);
    if (threadIdx.x == 0) {
        out[2105344] = (float)(1.25 * g_loss / (double)(NTOK * WIDTH));
        out[2105345] = 100.0f * s / (float)VOCAB;
    }
}

// ---------------- launch ----------------
extern "C" void kernel_launch(void* const* d_in, const int* in_sizes, int n_in,
                              void* d_out, int out_size) {
    const float* cls   = nullptr;
    const float* patch = nullptr;
    const float* W     = nullptr;
    for (int i = 0; i < n_in; i++) {
        if      (in_sizes[i] == NBATCH * WIDTH)          cls   = (const float*)d_in[i];
        else if (in_sizes[i] == NBATCH * WIDTH * 256)    patch = (const float*)d_in[i];
        else if (in_sizes[i] == VOCAB * WIDTH)           W     = (const float*)d_in[i];
    }
    float* out = (float*)d_out;

    cudaFuncSetAttribute(k_gemm_mma, cudaFuncAttributeMaxDynamicSharedMemorySize, DYN_SMEM);

    k_normalize<<<MPAD + VOCAB, 256>>>(cls, patch, W);
    dim3 grid(VOCAB / TN, MPAD / TM);   // (128, 65)
    k_gemm_mma<<<grid, 256, DYN_SMEM>>>();
    k_output<<<NTOK, 256>>>(cls, patch, W, out);
    k_finalize<<<1, 256>>>(out);
}

// round 13
// speedup vs baseline: 1.2398x; 1.0747x over previous
#include <cuda_runtime.h>
#include <cuda_bf16.h>

#define VOCAB   16384
#define WIDTH   256
#define NTOK    8224      // 32 * 257
#define MPAD    8320      // 65 * 128
#define NBATCH  32

#define KTOT    512       // stored per row: [hi(256) | lo(256)]
#define TM      128
#define TN      128
#define BK      64        // bf16 per k-slab => 128B rows
#define NSLAB   12        // 4x hi*hi + 4x hi*lo + 4x lo*hi
#define STAGE   32768     // A 16KB + B 16KB
#define B_OFF   16384
#define NSTAGE  3
#define DYN_SMEM (NSTAGE * STAGE)   // 96KB -> 2 CTAs/SM

// ---------------- scratch (device globals; no runtime alloc) ----------------
__device__ __align__(16) __nv_bfloat16 g_Abf[MPAD * KTOT];    // 8.5 MB
__device__ __align__(16) __nv_bfloat16 g_Bbf[VOCAB * KTOT];   // 16.8 MB
__device__ unsigned long long  g_best[NTOK];
__device__ int                 g_used[VOCAB];
__device__ double              g_loss;
__device__ unsigned            g_done;

// ---------------- helpers ----------------
__device__ __forceinline__ float block_reduce_sum_256(float v) {
    __shared__ float red[8];
    const int lane = threadIdx.x & 31;
    const int w    = threadIdx.x >> 5;
    #pragma unroll
    for (int o = 16; o > 0; o >>= 1) v += __shfl_xor_sync(0xffffffffu, v, o);
    if (lane == 0) red[w] = v;
    __syncthreads();
    float s = 0.f;
    #pragma unroll
    for (int i = 0; i < 8; i++) s += red[i];
    return s;
}
__device__ __forceinline__ unsigned int f2key(float v) {
    unsigned int u = __float_as_uint(v);
    return (u & 0x80000000u) ? ~u : (u | 0x80000000u);
}
__device__ __forceinline__ unsigned smem_u32(const void* p) {
    unsigned a;
    asm("{ .reg .u64 t; cvta.to.shared.u64 t, %1; cvt.u32.u64 %0, t; }" : "=r"(a) : "l"(p));
    return a;
}
__device__ __forceinline__ void cp16(unsigned dst, const void* src) {
    asm volatile("cp.async.cg.shared.global [%0], [%1], 16;" :: "r"(dst), "l"(src));
}
#define CP_COMMIT() asm volatile("cp.async.commit_group;" ::: "memory")
#define CP_WAIT1()  asm volatile("cp.async.wait_group 1;"  ::: "memory")
#define CP_WAIT0()  asm volatile("cp.async.wait_group 0;"  ::: "memory")

__device__ __forceinline__ void ldsm4(unsigned& r0, unsigned& r1, unsigned& r2, unsigned& r3,
                                      unsigned addr) {
    asm volatile("ldmatrix.sync.aligned.m8n8.x4.shared.b16 {%0,%1,%2,%3}, [%4];"
                 : "=r"(r0), "=r"(r1), "=r"(r2), "=r"(r3) : "r"(addr));
}
__device__ __forceinline__ void mma_bf16(float* d, const unsigned* a, const unsigned* b) {
    asm volatile(
        "mma.sync.aligned.m16n8k16.row.col.f32.bf16.bf16.f32 "
        "{%0,%1,%2,%3}, {%4,%5,%6,%7}, {%8,%9}, {%0,%1,%2,%3};"
        : "+f"(d[0]), "+f"(d[1]), "+f"(d[2]), "+f"(d[3])
        : "r"(a[0]), "r"(a[1]), "r"(a[2]), "r"(a[3]), "r"(b[0]), "r"(b[1]));
}

// slab t -> (A k-offset, B k-offset) in bf16 elements within a row
__device__ __forceinline__ void slab_off(int t, int& kA, int& kB) {
    kA = (t < 8) ? ((t & 3) << 6) : (((t - 8) << 6) + 256);            // hi,hi,lo
    kB = (t < 4) ? (t << 6) : ((t < 8) ? (((t - 4) << 6) + 256)        // hi,lo,hi
                                       : ((t - 8) << 6));
}

// ---------------- K1: gather + normalize + bf16 hi/lo split (+ state reset) ----------------
__global__ void k_normalize(const float* __restrict__ cls,
                            const float* __restrict__ patch,
                            const float* __restrict__ W) {
    const int r = blockIdx.x;
    const int c = threadIdx.x;
    float v = 0.f;
    __nv_bfloat16* dst; long long row;
    if (r < MPAD) {
        if (r < NTOK) {
            const int b = r / 257, j = r % 257;
            v = (j == 0) ? cls[b * WIDTH + c]
                         : patch[b * 65536 + c * 256 + (j - 1)];
        }
        dst = g_Abf; row = r;
        if (c == 0 && r < NTOK) g_best[r] = 0ull;
        if (r == 0 && c == 1)   g_loss   = 0.0;
        if (r == 0 && c == 2)   g_done   = 0u;
    } else {
        row = r - MPAD;
        v = W[row * WIDTH + c];
        dst = g_Bbf;
        if (c == 0) g_used[row] = 0;
    }
    const float s   = block_reduce_sum_256(v * v);
    const float inv = 1.f / fmaxf(sqrtf(s), 1e-12f);
    const float xn  = v * inv;
    const __nv_bfloat16 hi = __float2bfloat16(xn);
    const float lo = xn - __bfloat162float(hi);
    dst[row * KTOT + c]       = hi;
    dst[row * KTOT + 256 + c] = __float2bfloat16(lo);
}

// ---------------- stage loader: one (A-chunk, B-chunk) slab ----------------
__device__ __forceinline__ void load_slab(unsigned sb, int bm, int bn,
                                          int kA0, int kB0, int tid) {
    const int ck = tid & 7;            // 16B chunk (8 bf16) within 128B row
    const int r0 = tid >> 3;           // 0..31
    const unsigned cswz = (unsigned)(ck << 4);
    #pragma unroll
    for (int i = 0; i < 4; i++) {
        const int lr = r0 + 32 * i;
        const unsigned off = (unsigned)lr * 128u + (cswz ^ (((unsigned)lr & 7u) << 4));
        cp16(sb + off,         g_Abf + (long long)(bm + lr) * KTOT + kA0 + ck * 8);
        cp16(sb + B_OFF + off, g_Bbf + (long long)(bn + lr) * KTOT + kB0 + ck * 8);
    }
    CP_COMMIT();
}

// ---------------- K2: bf16 mma.sync GEMM (3-term hi/lo split) + argmax ----------------
// CTA 128x128, 8 warps 2(m) x 4(n), warp tile 64x32; 3-stage ring, 1 sync/slab
__global__ __launch_bounds__(256, 2)
void k_gemm_mma() {
    extern __shared__ char dsm[];

    const unsigned base = smem_u32(dsm);
    const int tid  = threadIdx.x;
    const int lane = tid & 31;
    const int warp = tid >> 5;
    const int wm   = (warp >> 2) * 64;       // warp m-base (2 warps in m)
    const int wn   = (warp & 3) * 32;        // warp n-base (4 warps in n)
    const int bn   = blockIdx.x * TN;
    const int bm   = blockIdx.y * TM;

    float d[4][4][4];
    #pragma unroll
    for (int i = 0; i < 4; i++)
        #pragma unroll
        for (int j = 0; j < 4; j++)
            #pragma unroll
            for (int k = 0; k < 4; k++) d[i][j][k] = 0.f;

    // ldmatrix lane addressing
    const int lsel = lane & 7;
    const int agrp_r = ((lane >> 3) & 1) * 8;   // A: matrices 1,3 -> +8 rows
    const int agrp_k = ((lane >> 4) & 1) * 16;  // A: matrices 2,3 -> +16B k
    const int bgrp_r = ((lane >> 4) & 1) * 8;   // B: matrices 2,3 -> +8 rows
    const int bgrp_k = ((lane >> 3) & 1) * 16;  // B: matrices 1,3 -> +16B k

    // prologue: slabs 0 and 1 into stages 0,1
    {
        int kA, kB;
        slab_off(0, kA, kB); load_slab(base,         bm, bn, kA, kB, tid);
        slab_off(1, kA, kB); load_slab(base + STAGE, bm, bn, kA, kB, tid);
    }

    int s_cur = 0, s_nxt = 2;           // stage of slab t, stage for slab t+2
    #pragma unroll 1
    for (int t = 0; t < NSLAB; t++) {
        const unsigned sA = base + s_cur * STAGE;
        const unsigned sB = sA + B_OFF;
        if (t < NSLAB - 1) CP_WAIT1(); else CP_WAIT0();   // slab t resident
        __syncthreads();   // also: everyone done reading the stage we refill below

        if (t + 2 < NSLAB) {            // refill stage s_nxt (= stage of slab t-1)
            int kA, kB;
            slab_off(t + 2, kA, kB);
            load_slab(base + s_nxt * STAGE, bm, bn, kA, kB, tid);
        }
        if (++s_cur == NSTAGE) s_cur = 0;
        if (++s_nxt == NSTAGE) s_nxt = 0;

        #pragma unroll
        for (int g = 0; g < 4; g++) {           // k16 groups within 64-k slab
            const int kb = g * 32;
            unsigned a[4][4], b[4][2];
            #pragma unroll
            for (int mt = 0; mt < 4; mt++) {
                const int row = wm + mt * 16 + lsel + agrp_r;
                const int kk  = kb + agrp_k;
                ldsm4(a[mt][0], a[mt][1], a[mt][2], a[mt][3],
                      sA + (unsigned)row * 128u + ((unsigned)kk ^ (((unsigned)row & 7u) << 4)));
            }
            #pragma unroll
            for (int np = 0; np < 2; np++) {
                const int row = wn + np * 16 + lsel + bgrp_r;
                const int kk  = kb + bgrp_k;
                unsigned r0, r1, r2, r3;
                ldsm4(r0, r1, r2, r3,
                      sB + (unsigned)row * 128u + ((unsigned)kk ^ (((unsigned)row & 7u) << 4)));
                b[np * 2 + 0][0] = r0; b[np * 2 + 0][1] = r1;
                b[np * 2 + 1][0] = r2; b[np * 2 + 1][1] = r3;
            }
            #pragma unroll
            for (int mt = 0; mt < 4; mt++)
                #pragma unroll
                for (int nt = 0; nt < 4; nt++)
                    mma_bf16(d[mt][nt], a[mt], b[nt]);
        }
    }

    // ---- fused argmax epilogue: quad shuffle-reduce + direct global atomicMax ----
    // lanes {4q..4q+3} hold the same row (lane>>2) with disjoint col ranges.
    #pragma unroll
    for (int mt = 0; mt < 4; mt++) {
        #pragma unroll
        for (int rh = 0; rh < 2; rh++) {        // d0/d1 = row, d2/d3 = row+8
            float bestv = -2.0f; int bestc = 0;
            #pragma unroll
            for (int nt = 0; nt < 4; nt++) {
                const int c0 = wn + nt * 8 + (lane & 3) * 2;  // ascending col order
                const float v0 = d[mt][nt][rh * 2 + 0];
                const float v1 = d[mt][nt][rh * 2 + 1];
                if (v0 > bestv) { bestv = v0; bestc = c0; }
                if (v1 > bestv) { bestv = v1; bestc = c0 + 1; }
            }
            unsigned long long pk =
                ((unsigned long long)f2key(bestv) << 32) |
                (unsigned long long)(0xFFFFFFFFu - (unsigned)(bn + bestc));
            // reduce over the 4-lane quad (max of packed key = correct argmax + tie-break)
            unsigned long long o1 = __shfl_xor_sync(0xffffffffu, pk, 1);
            if (o1 > pk) pk = o1;
            unsigned long long o2 = __shfl_xor_sync(0xffffffffu, pk, 2);
            if (o2 > pk) pk = o2;
            if ((lane & 3) == 0) {
                const int grow = bm + wm + mt * 16 + rh * 8 + (lane >> 2);
                if (grow < NTOK) atomicMax(&g_best[grow], pk);
            }
        }
    }
}

// ---------------- K3: gather W[idx], outputs, loss + usage; last block finalizes ----------------
// grid = NTOK/2 blocks, 256 threads; each block handles tokens 2i, 2i+1
__global__ void k_output(const float* __restrict__ cls,
                         const float* __restrict__ patch,
                         const float* __restrict__ W,
                         float* __restrict__ out) {
    __shared__ unsigned s_last;
    const int t0 = blockIdx.x * 2;
    const int t1 = t0 + 1;
    const int c  = threadIdx.x;
    const int b0 = t0 / 257, j0 = t0 % 257;
    const int b1 = t1 / 257, j1 = t1 % 257;

    const int code0 = (int)(0xFFFFFFFFu - (unsigned)(g_best[t0] & 0xFFFFFFFFull));
    const int code1 = (int)(0xFFFFFFFFu - (unsigned)(g_best[t1] & 0xFFFFFFFFull));
    const float w0 = W[code0 * WIDTH + c];
    const float w1 = W[code1 * WIDTH + c];
    const float x0 = (j0 == 0) ? cls[b0 * WIDTH + c] : patch[b0 * 65536 + c * 256 + (j0 - 1)];
    const float x1 = (j1 == 0) ? cls[b1 * WIDTH + c] : patch[b1 * 65536 + c * 256 + (j1 - 1)];
    const float d0 = w0 - x0, d1 = w1 - x1;
    const float s = block_reduce_sum_256(d0 * d0 + d1 * d1);
    if (c == 0) {
        atomicAdd(&g_loss, (double)s);
        g_used[code0] = 1;
        g_used[code1] = 1;
    }
    if (j0 == 0) out[b0 * WIDTH + c] = w0;
    else         out[8192 + b0 * 65536 + c * 256 + (j0 - 1)] = w0;
    if (j1 == 0) out[b1 * WIDTH + c] = w1;
    else         out[8192 + b1 * 65536 + c * 256 + (j1 - 1)] = w1;

    // ---- last-block-done: fold finalize here ----
    __syncthreads();
    if (c == 0) {
        __threadfence();
        s_last = (atomicAdd(&g_done, 1u) == (unsigned)(gridDim.x - 1)) ? 1u : 0u;
    }
    __syncthreads();
    if (s_last) {
        __threadfence();
        int cnt = 0;
        for (int i = c; i < VOCAB; i += 256) cnt += g_used[i];
        const float cs = block_reduce_sum_256((float)cnt);   // exact for <= 16384
        if (c == 0) {
            out[2105344] = (float)(1.25 * g_loss / (double)(NTOK * WIDTH));
            out[2105345] = 100.0f * cs / (float)VOCAB;
        }
    }
}

// ---------------- launch ----------------
extern "C" void kernel_launch(void* const* d_in, const int* in_sizes, int n_in,
                              void* d_out, int out_size) {
    const float* cls   = nullptr;
    const float* patch = nullptr;
    const float* W     = nullptr;
    for (int i = 0; i < n_in; i++) {
        if      (in_sizes[i] == NBATCH * WIDTH)          cls   = (const float*)d_in[i];
        else if (in_sizes[i] == NBATCH * WIDTH * 256)    patch = (const float*)d_in[i];
        else if (in_sizes[i] == VOCAB * WIDTH)           W     = (const float*)d_in[i];
    }
    float* out = (float*)d_out;

    cudaFuncSetAttribute(k_gemm_mma, cudaFuncAttributeMaxDynamicSharedMemorySize, DYN_SMEM);

    k_normalize<<<MPAD + VOCAB, 256>>>(cls, patch, W);
    dim3 grid(VOCAB / TN, MPAD / TM);   // (128, 65)
    k_gemm_mma<<<grid, 256, DYN_SMEM>>>();
    k_output<<<NTOK / 2, 256>>>(cls, patch, W, out);
}